// round 8
// baseline (speedup 1.0000x reference)
#include <cuda_runtime.h>
#include <cuda_bf16.h>
#include <cstdint>

#define BN_EPS 1e-5f

// ---------------- scratch (no allocations allowed) ----------------
__device__ float g_x1[200000 * 64];        // conv1 output (N x 64)
__device__ float g_x2[(32768 + 1) * 128];  // conv2 output (M x 128)
__device__ float g_stats[512];             // [sum | sumsq | a | d]

// ---------------- helpers ----------------
typedef unsigned long long ULL;
static __device__ __forceinline__ ULL pack2(float x) {
    ULL r; asm("mov.b64 %0, {%1, %1};" : "=l"(r) : "f"(x)); return r;
}
static __device__ __forceinline__ void fma2(ULL& acc, ULL a, ULL b) {
    asm("fma.rn.f32x2 %0, %1, %2, %0;" : "+l"(acc) : "l"(a), "l"(b));
}
static __device__ __forceinline__ float lo32(ULL v) { return __uint_as_float((unsigned)v); }
static __device__ __forceinline__ float hi32(ULL v) { return __uint_as_float((unsigned)(v >> 32)); }
static __device__ __forceinline__ void red_add2(float* p, float a, float b) {
    asm volatile("red.global.add.v2.f32 [%0], {%1,%2};" :: "l"(p), "f"(a), "f"(b) : "memory");
}
static __device__ __forceinline__ void mma_bf16(float* d, uint32_t a0, uint32_t a1,
                                                uint32_t a2, uint32_t a3,
                                                uint32_t b0, uint32_t b1) {
    asm volatile(
        "mma.sync.aligned.m16n8k16.row.col.f32.bf16.bf16.f32 "
        "{%0,%1,%2,%3}, {%4,%5,%6,%7}, {%8,%9}, {%0,%1,%2,%3};"
        : "+f"(d[0]), "+f"(d[1]), "+f"(d[2]), "+f"(d[3])
        : "r"(a0), "r"(a1), "r"(a2), "r"(a3), "r"(b0), "r"(b1));
}

// ============================================================================
// ENGINE F: fp32 FFMA2 (fma pipe). 256 thr; warp = 16 pairs x 64 couts.
// TILE = 128 (COUT=64) or 64 (COUT=128) pairs. A smem [CIN][TILE+4] transposed;
// W via __ldg (L1-resident). acc = 16 ULL. 3 blocks/SM.
// ============================================================================
template <int CIN, int COUT, bool BNIN>
__global__ __launch_bounds__(256, 3)
void conv_f(const float* __restrict__ fin, const float* __restrict__ W,
            const int* __restrict__ rin, const int* __restrict__ rout,
            float* __restrict__ out, int P, int n_in,
            const float* __restrict__ bnA, const float* __restrict__ bnD) {
    constexpr int TILE = (COUT == 64) ? 128 : 64;
    constexpr int ASTR = TILE + 4;
    constexpr int NPG = TILE / 16;
    constexpr int TPR = 256 / TILE;
    constexpr int CHUNK = CIN / TPR;

    const int k = blockIdx.y;
    const int rbase = k * P;
    if (blockIdx.x * TILE >= P) return;
    if (rin[rbase + blockIdx.x * TILE] == n_in) return;  // pads trail

    extern __shared__ float As[];
    __shared__ int s_in[TILE], s_out[TILE];

    const int tid = threadIdx.x;
    const int lane = tid & 31, wid = tid >> 5;
    const int p0 = (wid % NPG) * 16;
    const int c0 = (wid / NPG) * 64;
    const float* Wkc = W + (size_t)k * CIN * COUT + c0 + lane * 2;
    const int ntiles = (P + TILE - 1) / TILE;

    for (int t = blockIdx.x; t < ntiles; t += gridDim.x) {
        if (tid < TILE) {
            int idx = t * TILE + tid;
            s_in[tid] = (idx < P) ? rin[rbase + idx] : n_in;
            s_out[tid] = (idx < P) ? rout[rbase + idx] : 0;
        }
        __syncthreads();
        if (s_in[0] == n_in) break;

        // gather (+ fused BN/ReLU), transpose into As
        {
            int row = tid / TPR, cb = (tid % TPR) * CHUNK;
            int src = s_in[row];
            if (src == n_in) src = 0;          // pad: content irrelevant
            const float4* sp = (const float4*)(fin + (size_t)src * CIN + cb);
#pragma unroll
            for (int j = 0; j < CHUNK / 4; j++) {
                float4 v = sp[j];
                if (BNIN) {
                    float4 a4 = *(const float4*)(bnA + cb + 4 * j);
                    float4 d4 = *(const float4*)(bnD + cb + 4 * j);
                    v.x = fmaxf(fmaf(v.x, a4.x, d4.x), 0.f);
                    v.y = fmaxf(fmaf(v.y, a4.y, d4.y), 0.f);
                    v.z = fmaxf(fmaf(v.z, a4.z, d4.z), 0.f);
                    v.w = fmaxf(fmaf(v.w, a4.w, d4.w), 0.f);
                }
                int c = cb + 4 * j;
                As[(c + 0) * ASTR + row] = v.x;
                As[(c + 1) * ASTR + row] = v.y;
                As[(c + 2) * ASTR + row] = v.z;
                As[(c + 3) * ASTR + row] = v.w;
            }
        }
        __syncthreads();

        ULL acc[8][2];
#pragma unroll
        for (int i = 0; i < 8; i++) { acc[i][0] = 0ull; acc[i][1] = 0ull; }

#pragma unroll 2
        for (int cin = 0; cin < CIN; cin++) {
            float2 wv = __ldg((const float2*)(Wkc + (size_t)cin * COUT));
            ULL w0 = pack2(wv.x), w1 = pack2(wv.y);
            const ulonglong2* ar = (const ulonglong2*)(As + cin * ASTR + p0);
            ulonglong2 a01 = ar[0], a23 = ar[1], a45 = ar[2], a67 = ar[3];
            fma2(acc[0][0], a01.x, w0); fma2(acc[0][1], a01.x, w1);
            fma2(acc[1][0], a01.y, w0); fma2(acc[1][1], a01.y, w1);
            fma2(acc[2][0], a23.x, w0); fma2(acc[2][1], a23.x, w1);
            fma2(acc[3][0], a23.y, w0); fma2(acc[3][1], a23.y, w1);
            fma2(acc[4][0], a45.x, w0); fma2(acc[4][1], a45.x, w1);
            fma2(acc[5][0], a45.y, w0); fma2(acc[5][1], a45.y, w1);
            fma2(acc[6][0], a67.x, w0); fma2(acc[6][1], a67.x, w1);
            fma2(acc[7][0], a67.y, w0); fma2(acc[7][1], a67.y, w1);
        }

#pragma unroll
        for (int i = 0; i < 8; i++) {
            int pr = p0 + 2 * i;
            if (s_in[pr] != n_in)
                red_add2(out + (size_t)s_out[pr] * COUT + c0 + lane * 2,
                         lo32(acc[i][0]), lo32(acc[i][1]));
            if (s_in[pr + 1] != n_in)
                red_add2(out + (size_t)s_out[pr + 1] * COUT + c0 + lane * 2,
                         hi32(acc[i][0]), hi32(acc[i][1]));
        }
        __syncthreads();
    }
}

// ============================================================================
// ENGINE M: bf16 mma.sync 3-term split (tensor pipe). R5-proven layout.
// 256 thr = 8 warps; tile 128 pairs; warp = 16 pairs x all COUT.
// kbase offsets the rulebook column. BNIN fuses prev-stage BN into gather.
// ============================================================================
template <int CIN, int COUT, bool BNIN>
__global__ __launch_bounds__(256)
void conv_m(const float* __restrict__ fin, const float* __restrict__ W,
            const int* __restrict__ rin, const int* __restrict__ rout,
            float* __restrict__ out, int P, int n_in,
            const float* __restrict__ bnA, const float* __restrict__ bnD, int kbase) {
    constexpr int SA = 2 * CIN + 8;
    constexpr int NT = COUT / 8;
    constexpr int KS = CIN / 16;

    const int k = kbase + blockIdx.y;
    const int rbase = k * P;
    if ((blockIdx.x << 7) >= P) return;
    if (rin[rbase + (blockIdx.x << 7)] == n_in) return;

    extern __shared__ __nv_bfloat16 smem_bf[];
    __nv_bfloat16* As = smem_bf;              // 128 * SA
    __nv_bfloat16* Bs = smem_bf + 128 * SA;   // COUT * SA
    __shared__ int s_in[128], s_out[128];

    const int tid = threadIdx.x;

    const float* Wk = W + (size_t)k * CIN * COUT;
    for (int idx = tid; idx < CIN * COUT; idx += 256) {
        int cin = idx / COUT, cout = idx - cin * COUT;
        float w = Wk[idx];
        __nv_bfloat16 h = __float2bfloat16(w);
        __nv_bfloat16 l = __float2bfloat16(w - __bfloat162float(h));
        Bs[cout * SA + cin] = h;
        Bs[cout * SA + CIN + cin] = l;
    }

    const int lane = tid & 31, wid = tid >> 5;
    const int g = lane >> 2, q = lane & 3;
    const int wp0 = wid * 16;
    const int ntiles = (P + 127) >> 7;

    for (int t = blockIdx.x; t < ntiles; t += gridDim.x) {
        if (tid < 128) {
            int idx = (t << 7) + tid;
            s_in[tid] = (idx < P) ? rin[rbase + idx] : n_in;
            s_out[tid] = (idx < P) ? rout[rbase + idx] : 0;
        }
        __syncthreads();
        if (s_in[0] == n_in) break;

        {
            int row = tid >> 1, half = tid & 1;
            int src_row = s_in[row];
            if (src_row == n_in) src_row = 0;
            const int cb = half * (CIN / 2);
            const float4* src = (const float4*)(fin + (size_t)src_row * CIN + cb);
            __nv_bfloat16* da = As + row * SA + cb;
#pragma unroll
            for (int j = 0; j < CIN / 8; j++) {
                float4 vv = src[j];
                if (BNIN) {
                    float4 a4 = *(const float4*)(bnA + cb + 4 * j);
                    float4 d4 = *(const float4*)(bnD + cb + 4 * j);
                    vv.x = fmaxf(fmaf(vv.x, a4.x, d4.x), 0.f);
                    vv.y = fmaxf(fmaf(vv.y, a4.y, d4.y), 0.f);
                    vv.z = fmaxf(fmaf(vv.z, a4.z, d4.z), 0.f);
                    vv.w = fmaxf(fmaf(vv.w, a4.w, d4.w), 0.f);
                }
                __nv_bfloat16 hx = __float2bfloat16(vv.x), hy = __float2bfloat16(vv.y);
                __nv_bfloat16 hz = __float2bfloat16(vv.z), hw = __float2bfloat16(vv.w);
                __nv_bfloat162 h01 = __halves2bfloat162(hx, hy);
                __nv_bfloat162 h23 = __halves2bfloat162(hz, hw);
                __nv_bfloat162 l01 = __halves2bfloat162(
                    __float2bfloat16(vv.x - __bfloat162float(hx)),
                    __float2bfloat16(vv.y - __bfloat162float(hy)));
                __nv_bfloat162 l23 = __halves2bfloat162(
                    __float2bfloat16(vv.z - __bfloat162float(hz)),
                    __float2bfloat16(vv.w - __bfloat162float(hw)));
                *(uint2*)(da + 4 * j) = make_uint2(*(uint32_t*)&h01, *(uint32_t*)&h23);
                *(uint2*)(da + CIN + 4 * j) = make_uint2(*(uint32_t*)&l01, *(uint32_t*)&l23);
            }
        }
        __syncthreads();

        float d[NT][4];
#pragma unroll
        for (int n = 0; n < NT; n++) { d[n][0] = 0.f; d[n][1] = 0.f; d[n][2] = 0.f; d[n][3] = 0.f; }
        const __nv_bfloat16* A0 = As + (wp0 + g) * SA + q * 2;
        const __nv_bfloat16* B0 = Bs + g * SA + q * 2;
#pragma unroll
        for (int term = 0; term < 3; term++) {
            const int ka0 = (term == 2) ? CIN : 0;
            const int kb0 = (term == 1) ? CIN : 0;
#pragma unroll 1
            for (int s = 0; s < KS; s++) {
                const int ka = ka0 + s * 16, kb = kb0 + s * 16;
                uint32_t a0 = *(const uint32_t*)(A0 + ka);
                uint32_t a1 = *(const uint32_t*)(A0 + 8 * SA + ka);
                uint32_t a2 = *(const uint32_t*)(A0 + ka + 8);
                uint32_t a3 = *(const uint32_t*)(A0 + 8 * SA + ka + 8);
                const __nv_bfloat16* bp = B0 + kb;
#pragma unroll
                for (int n = 0; n < NT; n++) {
                    uint32_t b0 = *(const uint32_t*)(bp);
                    uint32_t b1 = *(const uint32_t*)(bp + 8);
                    mma_bf16(d[n], a0, a1, a2, a3, b0, b1);
                    bp += 8 * SA;
                }
            }
        }

        {
            int r0 = wp0 + g, r1 = r0 + 8;
            bool v0 = (s_in[r0] != n_in), v1 = (s_in[r1] != n_in);
            float* dst0 = out + (size_t)s_out[r0] * COUT + q * 2;
            float* dst1 = out + (size_t)s_out[r1] * COUT + q * 2;
#pragma unroll
            for (int n = 0; n < NT; n++) {
                if (v0) red_add2(dst0 + n * 8, d[n][0], d[n][1]);
                if (v1) red_add2(dst1 + n * 8, d[n][2], d[n][3]);
            }
        }
        __syncthreads();
    }
}

// ---------------- BatchNorm (training stats) + ReLU ----------------
template <int COUT>
__global__ void bn_stats(const float* __restrict__ x, int R, float* __restrict__ st) {
    __shared__ float ss[COUT], sq[COUT];
    int tid = threadIdx.x;
    if (tid < COUT) { ss[tid] = 0.f; sq[tid] = 0.f; }
    __syncthreads();
    int c = tid & (COUT - 1);
    constexpr int RPB = 256 / COUT;
    float s = 0.f, qq = 0.f;
    for (int r = blockIdx.x * RPB + tid / COUT; r < R; r += gridDim.x * RPB) {
        float v = x[(size_t)r * COUT + c];
        s += v; qq += v * v;
    }
    atomicAdd(&ss[c], s);
    atomicAdd(&sq[c], qq);
    __syncthreads();
    if (tid < COUT) { atomicAdd(&st[tid], ss[tid]); atomicAdd(&st[COUT + tid], sq[tid]); }
}

template <int COUT>
__global__ void bn_finalize(const float* __restrict__ g, const float* __restrict__ b,
                            float invR, float* __restrict__ st) {
    int c = threadIdx.x;
    if (c < COUT) {
        float mu = st[c] * invR;
        float var = st[COUT + c] * invR - mu * mu;
        float a = rsqrtf(var + BN_EPS) * g[c];
        st[2 * COUT + c] = a;
        st[3 * COUT + c] = b[c] - mu * a;
    }
}

template <int COUT>
__global__ void bn_apply_relu(float* __restrict__ x, int total4,
                              const float* __restrict__ st) {
    int i = blockIdx.x * blockDim.x + threadIdx.x;
    if (i >= total4) return;
    float4 v = reinterpret_cast<float4*>(x)[i];
    int c0 = (i * 4) & (COUT - 1);
    const float* A = st + 2 * COUT;
    const float* D = st + 3 * COUT;
    v.x = fmaxf(fmaf(v.x, A[c0 + 0], D[c0 + 0]), 0.f);
    v.y = fmaxf(fmaf(v.y, A[c0 + 1], D[c0 + 1]), 0.f);
    v.z = fmaxf(fmaf(v.z, A[c0 + 2], D[c0 + 2]), 0.f);
    v.w = fmaxf(fmaf(v.w, A[c0 + 3], D[c0 + 3]), 0.f);
    reinterpret_cast<float4*>(x)[i] = v;
}

// ---------------- launch ----------------
extern "C" void kernel_launch(void* const* d_in, const int* in_sizes, int n_in,
                              void* d_out, int out_size) {
    const float* feats = (const float*)d_in[0];
    const float* W1 = (const float*)d_in[1];
    const float* W2 = (const float*)d_in[2];
    const float* W3 = (const float*)d_in[3];
    const float* g1 = (const float*)d_in[4];
    const float* b1 = (const float*)d_in[5];
    const float* g2 = (const float*)d_in[6];
    const float* b2 = (const float*)d_in[7];
    const float* g3 = (const float*)d_in[8];
    const float* b3 = (const float*)d_in[9];
    const int* rb1i = (const int*)d_in[10];
    const int* rb1o = (const int*)d_in[11];
    const int* rb2i = (const int*)d_in[12];
    const int* rb2o = (const int*)d_in[13];
    const int* rb3i = (const int*)d_in[14];
    const int* rb3o = (const int*)d_in[15];

    const int N = in_sizes[0] / 64;
    const int M = out_size / 128;
    const int P1 = in_sizes[10] / 27;
    const int P2 = in_sizes[12] / 27;
    const int P3 = in_sizes[14] / 27;

    float *x1, *x2, *st;
    cudaGetSymbolAddress((void**)&x1, g_x1);
    cudaGetSymbolAddress((void**)&x2, g_x2);
    cudaGetSymbolAddress((void**)&st, g_stats);
    float* out = (float*)d_out;

    // one-time side-stream + events (host resources, no device memory)
    static cudaStream_t s1 = nullptr;
    static cudaEvent_t ev[4];
    if (!s1) {
        cudaStreamCreateWithFlags(&s1, cudaStreamNonBlocking);
        for (int i = 0; i < 4; i++) cudaEventCreateWithFlags(&ev[i], cudaEventDisableTiming);
    }

    const int SPLIT = 16;  // offsets [0,16) -> FFMA engine, [16,27) -> MMA engine

    const int smemF1 = 64 * 132 * 4;              // 33792
    const int smemF2 = 64 * 68 * 4;               // 17408
    const int smemF3 = 128 * 68 * 4;              // 34816
    const int smemM1 = (128 + 64) * (2 * 64 + 8) * 2;    // 52224
    const int smemM3 = (128 + 128) * (2 * 128 + 8) * 2;  // 135168
    cudaFuncSetAttribute((const void*)conv_m<64, 64, false>,
                         cudaFuncAttributeMaxDynamicSharedMemorySize, smemM1);
    cudaFuncSetAttribute((const void*)conv_m<128, 128, true>,
                         cudaFuncAttributeMaxDynamicSharedMemorySize, smemM3);

    // ---- stage 1: submanifold conv (N x 64) ----
    cudaMemsetAsync(x1, 0, (size_t)N * 64 * sizeof(float), 0);
    cudaEventRecord(ev[0], 0);
    cudaStreamWaitEvent(s1, ev[0], 0);
    conv_f<64, 64, false><<<dim3(64, SPLIT), 256, smemF1, 0>>>(
        feats, W1, rb1i, rb1o, x1, P1, N, nullptr, nullptr);
    conv_m<64, 64, false><<<dim3(48, 27 - SPLIT), 256, smemM1, s1>>>(
        feats, W1, rb1i, rb1o, x1, P1, N, nullptr, nullptr, SPLIT);
    cudaEventRecord(ev[1], s1);
    cudaStreamWaitEvent(0, ev[1], 0);

    cudaMemsetAsync(st, 0, 512 * sizeof(float), 0);
    bn_stats<64><<<148, 256, 0, 0>>>(x1, N, st);
    bn_finalize<64><<<1, 64, 0, 0>>>(g1, b1, 1.f / (float)N, st);

    // ---- stage 2: stride-2 conv (M x 128), all-FFMA, BN1 fused in gather ----
    cudaMemsetAsync(x2, 0, (size_t)M * 128 * sizeof(float), 0);
    conv_f<64, 128, true><<<dim3(32, 27), 256, smemF2, 0>>>(
        x1, W2, rb2i, rb2o, x2, P2, N, st + 128, st + 192);
    cudaMemsetAsync(st, 0, 512 * sizeof(float), 0);
    bn_stats<128><<<148, 256, 0, 0>>>(x2, M, st);
    bn_finalize<128><<<1, 128, 0, 0>>>(g2, b2, 1.f / (float)M, st);

    // ---- stage 3: submanifold conv (M x 128) -> d_out, BN2 fused ----
    cudaMemsetAsync(out, 0, (size_t)M * 128 * sizeof(float), 0);
    cudaEventRecord(ev[2], 0);
    cudaStreamWaitEvent(s1, ev[2], 0);
    conv_f<128, 128, true><<<dim3(40, SPLIT), 256, smemF3, 0>>>(
        x2, W3, rb3i, rb3o, out, P3, M, st + 256, st + 384);
    conv_m<128, 128, true><<<dim3(48, 27 - SPLIT), 256, smemM3, s1>>>(
        x2, W3, rb3i, rb3o, out, P3, M, st + 256, st + 384, SPLIT);
    cudaEventRecord(ev[3], s1);
    cudaStreamWaitEvent(0, ev[3], 0);

    cudaMemsetAsync(st, 0, 512 * sizeof(float), 0);
    bn_stats<128><<<148, 256, 0, 0>>>(out, M, st);
    bn_finalize<128><<<1, 128, 0, 0>>>(g3, b3, 1.f / (float)M, st);
    {
        int tot4 = M * 128 / 4;
        bn_apply_relu<128><<<(tot4 + 255) / 256, 256, 0, 0>>>(out, tot4, st);
    }
}

// round 9
// speedup vs baseline: 1.0348x; 1.0348x over previous
#include <cuda_runtime.h>
#include <cuda_bf16.h>
#include <cstdint>

#define BN_EPS 1e-5f

// ---------------- scratch (no allocations allowed) ----------------
__device__ float g_x1[200000 * 64];        // conv1 output (N x 64)
__device__ float g_x2[(32768 + 1) * 128];  // conv2 output (M x 128)
__device__ float g_stats[512];             // [sum | sumsq | a | d]

// ---------------- packed f32x2 helpers ----------------
typedef unsigned long long ULL;
static __device__ __forceinline__ ULL pack2(float x) {
    ULL r; asm("mov.b64 %0, {%1, %1};" : "=l"(r) : "f"(x)); return r;
}
static __device__ __forceinline__ void fma2(ULL& acc, ULL a, ULL b) {
    asm("fma.rn.f32x2 %0, %1, %2, %0;" : "+l"(acc) : "l"(a), "l"(b));
}
static __device__ __forceinline__ float lo32(ULL v) { return __uint_as_float((unsigned)v); }
static __device__ __forceinline__ float hi32(ULL v) { return __uint_as_float((unsigned)(v >> 32)); }
static __device__ __forceinline__ void red_add2(float* p, float a, float b) {
    asm volatile("red.global.add.v2.f32 [%0], {%1,%2};" :: "l"(p), "f"(a), "f"(b) : "memory");
}

// ============================================================================
// Sparse conv, R1-proven microkernel: tile = 64 pairs; warp = 16 pairs x 64
// couts (NCPT=2). COUT=64 -> 128 thr (4 warps); COUT=128 -> 256 thr (8 warps =
// 4 pair-groups x 2 cout-groups) for 2x warps/SM vs R1 on the big convs.
// A smem [CIN][68] transposed; W smem [CIN][COUT].
// BNIN fuses prev-stage BN+ReLU into the gather. Pad rows (rin==n_in,
// trailing) gather row 0 and never scatter. Liveness probe skips dead blocks.
// ============================================================================
template <int CIN, int COUT, bool BNIN>
__global__ __launch_bounds__((COUT == 64) ? 128 : 256)
void conv_ffma(const float* __restrict__ fin, const float* __restrict__ W,
               const int* __restrict__ rin, const int* __restrict__ rout,
               float* __restrict__ out, int P, int n_in,
               const float* __restrict__ bnA, const float* __restrict__ bnD) {
    constexpr int NTHR = (COUT == 64) ? 128 : 256;
    constexpr int ASTR = 68;
    constexpr int TPR = NTHR / 64;      // gather threads per pair row
    constexpr int CHUNK = CIN / TPR;

    const int k = blockIdx.y;
    const int rbase = k * P;
    if (blockIdx.x * 64 >= P) return;
    if (rin[rbase + blockIdx.x * 64] == n_in) return;   // pads trail

    extern __shared__ float sm[];
    float* As = sm;                     // CIN * 68
    float* Ws = sm + CIN * ASTR;        // CIN * COUT
    __shared__ int s_in[64], s_out[64];

    const int tid = threadIdx.x;

    // ---- cache W_k ----
    {
        const float4* wg = (const float4*)(W + (size_t)k * CIN * COUT);
        float4* wd = (float4*)Ws;
        for (int i = tid; i < CIN * COUT / 4; i += NTHR) wd[i] = wg[i];
    }

    const int lane = tid & 31, wid = tid >> 5;
    const int p0 = (wid & 3) * 16;      // warp's 16 pairs
    const int c0 = (wid >> 2) * 64;     // warp's cout half (0 for COUT=64)
    const int ntiles = (P + 63) >> 6;

    for (int t = blockIdx.x; t < ntiles; t += gridDim.x) {
        if (tid < 64) {
            int idx = (t << 6) + tid;
            s_in[tid] = (idx < P) ? rin[rbase + idx] : n_in;
            s_out[tid] = (idx < P) ? rout[rbase + idx] : 0;
        }
        __syncthreads();
        if (s_in[0] == n_in) break;

        // ---- gather (+ fused BN/ReLU), transpose into As ----
        {
            int row = tid / TPR, cb = (tid % TPR) * CHUNK;
            int src = s_in[row];
            if (src == n_in) src = 0;   // pad row: content irrelevant
            const float4* sp = (const float4*)(fin + (size_t)src * CIN + cb);
#pragma unroll
            for (int j = 0; j < CHUNK / 4; j++) {
                float4 v = sp[j];
                if (BNIN) {
                    float4 a4 = *(const float4*)(bnA + cb + 4 * j);
                    float4 d4 = *(const float4*)(bnD + cb + 4 * j);
                    v.x = fmaxf(fmaf(v.x, a4.x, d4.x), 0.f);
                    v.y = fmaxf(fmaf(v.y, a4.y, d4.y), 0.f);
                    v.z = fmaxf(fmaf(v.z, a4.z, d4.z), 0.f);
                    v.w = fmaxf(fmaf(v.w, a4.w, d4.w), 0.f);
                }
                int c = cb + 4 * j;
                As[(c + 0) * ASTR + row] = v.x;
                As[(c + 1) * ASTR + row] = v.y;
                As[(c + 2) * ASTR + row] = v.z;
                As[(c + 3) * ASTR + row] = v.w;
            }
        }
        __syncthreads();

        // ---- GEMM: 16 pairs x 64 couts per warp, packed f32x2 ----
        ULL acc[8][2];
#pragma unroll
        for (int i = 0; i < 8; i++) { acc[i][0] = 0ull; acc[i][1] = 0ull; }

#pragma unroll 4
        for (int cin = 0; cin < CIN; cin++) {
            float2 wv = *(const float2*)(Ws + cin * COUT + c0 + lane * 2);
            ULL w0 = pack2(wv.x), w1 = pack2(wv.y);
            const ulonglong2* ar = (const ulonglong2*)(As + cin * ASTR + p0);
            ulonglong2 a01 = ar[0], a23 = ar[1], a45 = ar[2], a67 = ar[3];
            fma2(acc[0][0], a01.x, w0); fma2(acc[0][1], a01.x, w1);
            fma2(acc[1][0], a01.y, w0); fma2(acc[1][1], a01.y, w1);
            fma2(acc[2][0], a23.x, w0); fma2(acc[2][1], a23.x, w1);
            fma2(acc[3][0], a23.y, w0); fma2(acc[3][1], a23.y, w1);
            fma2(acc[4][0], a45.x, w0); fma2(acc[4][1], a45.x, w1);
            fma2(acc[5][0], a45.y, w0); fma2(acc[5][1], a45.y, w1);
            fma2(acc[6][0], a67.x, w0); fma2(acc[6][1], a67.x, w1);
            fma2(acc[7][0], a67.y, w0); fma2(acc[7][1], a67.y, w1);
        }

        // ---- scatter: acc[i] = pairs (p0+2i, p0+2i+1), couts c0+lane*2(+1) ----
#pragma unroll
        for (int i = 0; i < 8; i++) {
            int pr = p0 + 2 * i;
            if (s_in[pr] != n_in)
                red_add2(out + (size_t)s_out[pr] * COUT + c0 + lane * 2,
                         lo32(acc[i][0]), lo32(acc[i][1]));
            if (s_in[pr + 1] != n_in)
                red_add2(out + (size_t)s_out[pr + 1] * COUT + c0 + lane * 2,
                         hi32(acc[i][0]), hi32(acc[i][1]));
        }
        __syncthreads();
    }
}

// ---------------- BatchNorm (training stats) + ReLU ----------------
template <int COUT>
__global__ void bn_stats(const float* __restrict__ x, int R, float* __restrict__ st) {
    __shared__ float ss[COUT], sq[COUT];
    int tid = threadIdx.x;
    if (tid < COUT) { ss[tid] = 0.f; sq[tid] = 0.f; }
    __syncthreads();
    int c = tid & (COUT - 1);
    constexpr int RPB = 256 / COUT;
    float s = 0.f, qq = 0.f;
    for (int r = blockIdx.x * RPB + tid / COUT; r < R; r += gridDim.x * RPB) {
        float v = x[(size_t)r * COUT + c];
        s += v; qq += v * v;
    }
    atomicAdd(&ss[c], s);
    atomicAdd(&sq[c], qq);
    __syncthreads();
    if (tid < COUT) { atomicAdd(&st[tid], ss[tid]); atomicAdd(&st[COUT + tid], sq[tid]); }
}

template <int COUT>
__global__ void bn_finalize(const float* __restrict__ g, const float* __restrict__ b,
                            float invR, float* __restrict__ st) {
    int c = threadIdx.x;
    if (c < COUT) {
        float mu = st[c] * invR;
        float var = st[COUT + c] * invR - mu * mu;
        float a = rsqrtf(var + BN_EPS) * g[c];
        st[2 * COUT + c] = a;
        st[3 * COUT + c] = b[c] - mu * a;
    }
}

template <int COUT>
__global__ void bn_apply_relu(float* __restrict__ x, int total4,
                              const float* __restrict__ st) {
    int i = blockIdx.x * blockDim.x + threadIdx.x;
    if (i >= total4) return;
    float4 v = reinterpret_cast<float4*>(x)[i];
    int c0 = (i * 4) & (COUT - 1);
    const float* A = st + 2 * COUT;
    const float* D = st + 3 * COUT;
    v.x = fmaxf(fmaf(v.x, A[c0 + 0], D[c0 + 0]), 0.f);
    v.y = fmaxf(fmaf(v.y, A[c0 + 1], D[c0 + 1]), 0.f);
    v.z = fmaxf(fmaf(v.z, A[c0 + 2], D[c0 + 2]), 0.f);
    v.w = fmaxf(fmaf(v.w, A[c0 + 3], D[c0 + 3]), 0.f);
    reinterpret_cast<float4*>(x)[i] = v;
}

// ---------------- launch ----------------
extern "C" void kernel_launch(void* const* d_in, const int* in_sizes, int n_in,
                              void* d_out, int out_size) {
    const float* feats = (const float*)d_in[0];
    const float* W1 = (const float*)d_in[1];
    const float* W2 = (const float*)d_in[2];
    const float* W3 = (const float*)d_in[3];
    const float* g1 = (const float*)d_in[4];
    const float* b1 = (const float*)d_in[5];
    const float* g2 = (const float*)d_in[6];
    const float* b2 = (const float*)d_in[7];
    const float* g3 = (const float*)d_in[8];
    const float* b3 = (const float*)d_in[9];
    const int* rb1i = (const int*)d_in[10];
    const int* rb1o = (const int*)d_in[11];
    const int* rb2i = (const int*)d_in[12];
    const int* rb2o = (const int*)d_in[13];
    const int* rb3i = (const int*)d_in[14];
    const int* rb3o = (const int*)d_in[15];

    const int N = in_sizes[0] / 64;
    const int M = out_size / 128;
    const int P1 = in_sizes[10] / 27;
    const int P2 = in_sizes[12] / 27;
    const int P3 = in_sizes[14] / 27;

    float *x1, *x2, *st;
    cudaGetSymbolAddress((void**)&x1, g_x1);
    cudaGetSymbolAddress((void**)&x2, g_x2);
    cudaGetSymbolAddress((void**)&st, g_stats);
    float* out = (float*)d_out;

    const int smem1 = (64 * 68 + 64 * 64) * 4;      // 33792
    const int smem2 = (64 * 68 + 64 * 128) * 4;     // 50176
    const int smem3 = (128 * 68 + 128 * 128) * 4;   // 100352
    cudaFuncSetAttribute((const void*)conv_ffma<64, 64, false>,
                         cudaFuncAttributeMaxDynamicSharedMemorySize, smem1);
    cudaFuncSetAttribute((const void*)conv_ffma<64, 128, true>,
                         cudaFuncAttributeMaxDynamicSharedMemorySize, smem2);
    cudaFuncSetAttribute((const void*)conv_ffma<128, 128, true>,
                         cudaFuncAttributeMaxDynamicSharedMemorySize, smem3);

    // ---- stage 1: submanifold conv (N x 64), raw input ----
    cudaMemsetAsync(x1, 0, (size_t)N * 64 * sizeof(float), 0);
    conv_ffma<64, 64, false><<<dim3(128, 27), 128, smem1, 0>>>(
        feats, W1, rb1i, rb1o, x1, P1, N, nullptr, nullptr);
    cudaMemsetAsync(st, 0, 512 * sizeof(float), 0);
    bn_stats<64><<<148, 256, 0, 0>>>(x1, N, st);
    bn_finalize<64><<<1, 64, 0, 0>>>(g1, b1, 1.f / (float)N, st);
    // BN1 apply+ReLU fused into conv2 gather (a at st+128, d at st+192)

    // ---- stage 2: stride-2 conv (M x 128), BN1 fused ----
    cudaMemsetAsync(x2, 0, (size_t)M * 128 * sizeof(float), 0);
    conv_ffma<64, 128, true><<<dim3(64, 27), 256, smem2, 0>>>(
        x1, W2, rb2i, rb2o, x2, P2, N, st + 128, st + 192);
    cudaMemsetAsync(st, 0, 512 * sizeof(float), 0);
    bn_stats<128><<<148, 256, 0, 0>>>(x2, M, st);
    bn_finalize<128><<<1, 128, 0, 0>>>(g2, b2, 1.f / (float)M, st);
    // BN2 apply+ReLU fused into conv3 gather (a at st+256, d at st+384)

    // ---- stage 3: submanifold conv (M x 128) -> d_out, BN2 fused ----
    cudaMemsetAsync(out, 0, (size_t)M * 128 * sizeof(float), 0);
    conv_ffma<128, 128, true><<<dim3(64, 27), 256, smem3, 0>>>(
        x2, W3, rb3i, rb3o, out, P3, M, st + 256, st + 384);
    cudaMemsetAsync(st, 0, 512 * sizeof(float), 0);
    bn_stats<128><<<148, 256, 0, 0>>>(out, M, st);
    bn_finalize<128><<<1, 128, 0, 0>>>(g3, b3, 1.f / (float)M, st);
    {
        int tot4 = M * 128 / 4;
        bn_apply_relu<128><<<(tot4 + 255) / 256, 256, 0, 0>>>(out, tot4, st);
    }
}

// round 10
// speedup vs baseline: 1.3683x; 1.3222x over previous
#include <cuda_runtime.h>
#include <cuda_bf16.h>
#include <cstdint>

#define BN_EPS 1e-5f

// ---------------- scratch (no allocations allowed) ----------------
__device__ float g_x1[200000 * 64];        // conv1 output (N x 64)
__device__ float g_x2[(32768 + 1) * 128];  // conv2 output (M x 128)
__device__ float g_stats[512];             // [sum | sumsq | a | d]

// ---------------- packed f32x2 helpers ----------------
typedef unsigned long long ULL;
static __device__ __forceinline__ ULL pack2(float x) {
    ULL r; asm("mov.b64 %0, {%1, %1};" : "=l"(r) : "f"(x)); return r;
}
static __device__ __forceinline__ void fma2(ULL& acc, ULL a, ULL b) {
    asm("fma.rn.f32x2 %0, %1, %2, %0;" : "+l"(acc) : "l"(a), "l"(b));
}
static __device__ __forceinline__ float lo32(ULL v) { return __uint_as_float((unsigned)v); }
static __device__ __forceinline__ float hi32(ULL v) { return __uint_as_float((unsigned)(v >> 32)); }
static __device__ __forceinline__ void red_add4(float* p, float a, float b, float c, float d) {
    asm volatile("red.global.add.v4.f32 [%0], {%1,%2,%3,%4};"
                 :: "l"(p), "f"(a), "f"(b), "f"(c), "f"(d) : "memory");
}
static __device__ __forceinline__ void red_add2(float* p, float a, float b) {
    asm volatile("red.global.add.v2.f32 [%0], {%1,%2};" :: "l"(p), "f"(a), "f"(b) : "memory");
}

// ============================================================================
// Sparse conv — the R1-proven 1560us shape, exactly:
// 128 threads = 4 warps; tile = 64 pairs; warp = 16 pairs x ALL couts
// (NCPT = COUT/32: 2 or 4). A smem [CIN][68] transposed; W smem [CIN][COUT].
// Inner loop: 4 broadcast LDS.128 for A, one float4/float2 W load per lane,
// 8*NCPT FFMA2 per cin (NCPT=4: 32 FFMA2 -> LDS latency fully hidden).
// Additions vs R1: liveness early-exit probe; optional fused BN+ReLU of the
// previous stage in the gather; clamped pad-row gather (no OOB pointers).
// ============================================================================
template <int CIN, int COUT, bool BNIN>
__global__ __launch_bounds__(128)
void conv_scatter(const float* __restrict__ fin, const float* __restrict__ W,
                  const int* __restrict__ rin, const int* __restrict__ rout,
                  float* __restrict__ out, int P, int n_in,
                  const float* __restrict__ bnA, const float* __restrict__ bnD) {
    constexpr int NCPT = COUT / 32;   // couts per thread (2 or 4)
    constexpr int ASTR = 68;          // A-tile stride (pairs dim)

    const int k = blockIdx.y;
    const int rbase = k * P;
    // liveness probe: pads trail within an offset; first tile dead => all dead
    if ((blockIdx.x << 6) >= P) return;
    if (rin[rbase + (blockIdx.x << 6)] == n_in) return;

    extern __shared__ float sm[];
    float* Ws = sm;                   // CIN*COUT
    float* As = sm + CIN * COUT;      // CIN * ASTR
    __shared__ int s_in[64];
    __shared__ int s_out[64];

    const int tid = threadIdx.x;

    // cache W_k in SMEM
    {
        const float4* wg = reinterpret_cast<const float4*>(W + (size_t)k * CIN * COUT);
        float4* ws4 = reinterpret_cast<float4*>(Ws);
        for (int i = tid; i < CIN * COUT / 4; i += 128) ws4[i] = wg[i];
    }

    const int lane = tid & 31;
    const int wid = tid >> 5;
    const int p0 = wid * 16;          // each warp: 16 pairs
    const int ntiles = (P + 63) >> 6;

    for (int t = blockIdx.x; t < ntiles; t += gridDim.x) {
        const int base = t << 6;
        if (tid < 64) {
            int idx = base + tid;
            s_in[tid]  = (idx < P) ? rin[rbase + idx]  : n_in;
            s_out[tid] = (idx < P) ? rout[rbase + idx] : 0;
        }
        __syncthreads();
        if (s_in[0] == n_in) break;   // pads trail: no more live tiles

        // gather A tile (+ fused BN/ReLU), transposed: As[cin][pair]
#pragma unroll
        for (int h = 0; h < 2; h++) {
            int p = (tid >> 2) + h * 32;
            int row = s_in[p];
            if (row == n_in) row = 0;  // pad row: content irrelevant, never scattered
            const float4* frow = reinterpret_cast<const float4*>(fin + (size_t)row * CIN);
#pragma unroll
            for (int j = 0; j < CIN / 16; j++) {
                int c4 = (tid & 3) + j * 4;
                float4 val = frow[c4];
                if (BNIN) {
                    float4 a4 = *(const float4*)(bnA + c4 * 4);
                    float4 d4 = *(const float4*)(bnD + c4 * 4);
                    val.x = fmaxf(fmaf(val.x, a4.x, d4.x), 0.f);
                    val.y = fmaxf(fmaf(val.y, a4.y, d4.y), 0.f);
                    val.z = fmaxf(fmaf(val.z, a4.z, d4.z), 0.f);
                    val.w = fmaxf(fmaf(val.w, a4.w, d4.w), 0.f);
                }
                As[(c4 * 4 + 0) * ASTR + p] = val.x;
                As[(c4 * 4 + 1) * ASTR + p] = val.y;
                As[(c4 * 4 + 2) * ASTR + p] = val.z;
                As[(c4 * 4 + 3) * ASTR + p] = val.w;
            }
        }
        __syncthreads();

        ULL acc[8][NCPT];
#pragma unroll
        for (int i = 0; i < 8; i++)
#pragma unroll
            for (int c = 0; c < NCPT; c++) acc[i][c] = 0ull;

#pragma unroll 4
        for (int cin = 0; cin < CIN; cin++) {
            const float* ar = As + cin * ASTR + p0;
            ulonglong2 a01 = *reinterpret_cast<const ulonglong2*>(ar);
            ulonglong2 a23 = *reinterpret_cast<const ulonglong2*>(ar + 4);
            ulonglong2 a45 = *reinterpret_cast<const ulonglong2*>(ar + 8);
            ulonglong2 a67 = *reinterpret_cast<const ulonglong2*>(ar + 12);
            ULL av[8] = {a01.x, a01.y, a23.x, a23.y, a45.x, a45.y, a67.x, a67.y};
            ULL wp[NCPT];
            if constexpr (NCPT == 4) {
                float4 wv = *reinterpret_cast<const float4*>(Ws + cin * COUT + lane * 4);
                wp[0] = pack2(wv.x); wp[1] = pack2(wv.y);
                wp[2] = pack2(wv.z); wp[3] = pack2(wv.w);
            } else {
                float2 wv = *reinterpret_cast<const float2*>(Ws + cin * COUT + lane * 2);
                wp[0] = pack2(wv.x); wp[1] = pack2(wv.y);
            }
#pragma unroll
            for (int i = 0; i < 8; i++)
#pragma unroll
                for (int c = 0; c < NCPT; c++) fma2(acc[i][c], av[i], wp[c]);
        }

        // scatter-add (outputs distinct within an offset; atomics across offsets)
#pragma unroll
        for (int i = 0; i < 8; i++) {
            int p = p0 + 2 * i;
            if (s_in[p] != n_in) {
                float* dst = out + (size_t)s_out[p] * COUT + lane * NCPT;
                if constexpr (NCPT == 4)
                    red_add4(dst, lo32(acc[i][0]), lo32(acc[i][1]),
                                  lo32(acc[i][2]), lo32(acc[i][3]));
                else
                    red_add2(dst, lo32(acc[i][0]), lo32(acc[i][1]));
            }
            if (s_in[p + 1] != n_in) {
                float* dst = out + (size_t)s_out[p + 1] * COUT + lane * NCPT;
                if constexpr (NCPT == 4)
                    red_add4(dst, hi32(acc[i][0]), hi32(acc[i][1]),
                                  hi32(acc[i][2]), hi32(acc[i][3]));
                else
                    red_add2(dst, hi32(acc[i][0]), hi32(acc[i][1]));
            }
        }
        __syncthreads();
    }
}

// ---------------- BatchNorm (training stats) + ReLU ----------------
template <int COUT>
__global__ void bn_stats(const float* __restrict__ x, int R, float* __restrict__ st) {
    __shared__ float ss[COUT], sq[COUT];
    int tid = threadIdx.x;
    if (tid < COUT) { ss[tid] = 0.f; sq[tid] = 0.f; }
    __syncthreads();
    int c = tid & (COUT - 1);
    constexpr int RPB = 256 / COUT;
    float s = 0.f, qq = 0.f;
    for (int r = blockIdx.x * RPB + tid / COUT; r < R; r += gridDim.x * RPB) {
        float v = x[(size_t)r * COUT + c];
        s += v; qq += v * v;
    }
    atomicAdd(&ss[c], s);
    atomicAdd(&sq[c], qq);
    __syncthreads();
    if (tid < COUT) { atomicAdd(&st[tid], ss[tid]); atomicAdd(&st[COUT + tid], sq[tid]); }
}

template <int COUT>
__global__ void bn_finalize(const float* __restrict__ g, const float* __restrict__ b,
                            float invR, float* __restrict__ st) {
    int c = threadIdx.x;
    if (c < COUT) {
        float mu = st[c] * invR;
        float var = st[COUT + c] * invR - mu * mu;
        float a = rsqrtf(var + BN_EPS) * g[c];
        st[2 * COUT + c] = a;
        st[3 * COUT + c] = b[c] - mu * a;
    }
}

template <int COUT>
__global__ void bn_apply_relu(float* __restrict__ x, int total4,
                              const float* __restrict__ st) {
    int i = blockIdx.x * blockDim.x + threadIdx.x;
    if (i >= total4) return;
    float4 v = reinterpret_cast<float4*>(x)[i];
    int c0 = (i * 4) & (COUT - 1);
    const float* A = st + 2 * COUT;
    const float* D = st + 3 * COUT;
    v.x = fmaxf(fmaf(v.x, A[c0 + 0], D[c0 + 0]), 0.f);
    v.y = fmaxf(fmaf(v.y, A[c0 + 1], D[c0 + 1]), 0.f);
    v.z = fmaxf(fmaf(v.z, A[c0 + 2], D[c0 + 2]), 0.f);
    v.w = fmaxf(fmaf(v.w, A[c0 + 3], D[c0 + 3]), 0.f);
    reinterpret_cast<float4*>(x)[i] = v;
}

// ---------------- launch ----------------
extern "C" void kernel_launch(void* const* d_in, const int* in_sizes, int n_in,
                              void* d_out, int out_size) {
    const float* feats = (const float*)d_in[0];
    const float* W1 = (const float*)d_in[1];
    const float* W2 = (const float*)d_in[2];
    const float* W3 = (const float*)d_in[3];
    const float* g1 = (const float*)d_in[4];
    const float* b1 = (const float*)d_in[5];
    const float* g2 = (const float*)d_in[6];
    const float* b2 = (const float*)d_in[7];
    const float* g3 = (const float*)d_in[8];
    const float* b3 = (const float*)d_in[9];
    const int* rb1i = (const int*)d_in[10];
    const int* rb1o = (const int*)d_in[11];
    const int* rb2i = (const int*)d_in[12];
    const int* rb2o = (const int*)d_in[13];
    const int* rb3i = (const int*)d_in[14];
    const int* rb3o = (const int*)d_in[15];

    const int N = in_sizes[0] / 64;
    const int M = out_size / 128;
    const int P1 = in_sizes[10] / 27;
    const int P2 = in_sizes[12] / 27;
    const int P3 = in_sizes[14] / 27;

    float *x1, *x2, *st;
    cudaGetSymbolAddress((void**)&x1, g_x1);
    cudaGetSymbolAddress((void**)&x2, g_x2);
    cudaGetSymbolAddress((void**)&st, g_stats);
    float* out = (float*)d_out;

    const int smem1 = (64 * 64 + 64 * 68) * 4;      // 33792
    const int smem2 = (64 * 128 + 64 * 68) * 4;     // 50176
    const int smem3 = (128 * 128 + 128 * 68) * 4;   // 100352
    cudaFuncSetAttribute((const void*)conv_scatter<64, 64, false>,
                         cudaFuncAttributeMaxDynamicSharedMemorySize, smem1);
    cudaFuncSetAttribute((const void*)conv_scatter<64, 128, true>,
                         cudaFuncAttributeMaxDynamicSharedMemorySize, smem2);
    cudaFuncSetAttribute((const void*)conv_scatter<128, 128, true>,
                         cudaFuncAttributeMaxDynamicSharedMemorySize, smem3);

    // ---- stage 1: submanifold conv (N x 64), raw input ----
    cudaMemsetAsync(x1, 0, (size_t)N * 64 * sizeof(float), 0);
    conv_scatter<64, 64, false><<<dim3(160, 27), 128, smem1, 0>>>(
        feats, W1, rb1i, rb1o, x1, P1, N, nullptr, nullptr);
    cudaMemsetAsync(st, 0, 512 * sizeof(float), 0);
    bn_stats<64><<<148, 256, 0, 0>>>(x1, N, st);
    bn_finalize<64><<<1, 64, 0, 0>>>(g1, b1, 1.f / (float)N, st);
    // BN1 apply+ReLU fused into conv2 gather (a at st+128, d at st+192)

    // ---- stage 2: stride-2 conv (M x 128), BN1 fused ----
    cudaMemsetAsync(x2, 0, (size_t)M * 128 * sizeof(float), 0);
    conv_scatter<64, 128, true><<<dim3(128, 27), 128, smem2, 0>>>(
        x1, W2, rb2i, rb2o, x2, P2, N, st + 128, st + 192);
    cudaMemsetAsync(st, 0, 512 * sizeof(float), 0);
    bn_stats<128><<<148, 256, 0, 0>>>(x2, M, st);
    bn_finalize<128><<<1, 128, 0, 0>>>(g2, b2, 1.f / (float)M, st);
    // BN2 apply+ReLU fused into conv3 gather (a at st+256, d at st+384)

    // ---- stage 3: submanifold conv (M x 128) -> d_out, BN2 fused ----
    cudaMemsetAsync(out, 0, (size_t)M * 128 * sizeof(float), 0);
    conv_scatter<128, 128, true><<<dim3(128, 27), 128, smem3, 0>>>(
        x2, W3, rb3i, rb3o, out, P3, M, st + 256, st + 384);
    cudaMemsetAsync(st, 0, 512 * sizeof(float), 0);
    bn_stats<128><<<148, 256, 0, 0>>>(out, M, st);
    bn_finalize<128><<<1, 128, 0, 0>>>(g3, b3, 1.f / (float)M, st);
    {
        int tot4 = M * 128 / 4;
        bn_apply_relu<128><<<(tot4 + 255) / 256, 256, 0, 0>>>(out, tot4, st);
    }
}